// round 1
// baseline (speedup 1.0000x reference)
#include <cuda_runtime.h>
#include <cstdint>

#define Bb   4
#define Tt   12
#define Nn   512
#define DIM  128
#define Hh   4
#define DK   32
#define ROWS (Bb*Tt*Nn)          // 24576

// ---------------- scratch (no allocations allowed) ----------------
__device__ float g_Q[ROWS * DIM];
__device__ float g_K[ROWS * DIM];
__device__ float g_V[ROWS * DIM];
__device__ float g_X[ROWS * DIM];

// ---------------- GEMM: Y[r][e] = sum_d X[r][d] * W[e][d] + bias[e] ----------------
// CTA: 128 rows x 128 cols, 256 threads. warp w -> rows w*16..w*16+15, lane -> cols lane*4..+3
#define XS_STRIDE 132
#define SMEM_GEMM ((128*XS_STRIDE + 128*XS_STRIDE) * 4)

__global__ __launch_bounds__(256, 1)
void gemm_kernel(const float* __restrict__ X, const float* __restrict__ W,
                 const float* __restrict__ bias, float* __restrict__ Y)
{
    extern __shared__ float sm[];
    float* Xs = sm;                       // [128][132] natural
    float* Wt = sm + 128 * XS_STRIDE;     // [128 k][132 e] transposed

    const int tid  = threadIdx.x;
    const int w    = tid >> 5;
    const int lane = tid & 31;
    const size_t row0 = (size_t)blockIdx.x * 128;

    // load X tile (coalesced, conflict-free STS)
    #pragma unroll
    for (int it = 0; it < 16; it++) {
        int idx = it * 256 + tid;
        int r = idx >> 5, k4 = idx & 31;
        *(float4*)(Xs + r * XS_STRIDE + k4 * 4) =
            *(const float4*)(X + (row0 + r) * DIM + k4 * 4);
    }
    // load W transposed: W[e][k] -> Wt[k][e]
    #pragma unroll
    for (int it = 0; it < 16; it++) {
        int idx = it * 256 + tid;
        int j  = idx & 7;
        int e  = (idx >> 3) & 127;
        int k4 = ((idx >> 10) << 3) | j;
        float4 v = *(const float4*)(W + e * DIM + k4 * 4);
        Wt[(k4 * 4 + 0) * XS_STRIDE + e] = v.x;
        Wt[(k4 * 4 + 1) * XS_STRIDE + e] = v.y;
        Wt[(k4 * 4 + 2) * XS_STRIDE + e] = v.z;
        Wt[(k4 * 4 + 3) * XS_STRIDE + e] = v.w;
    }
    __syncthreads();

    float acc[16][4];
    #pragma unroll
    for (int i = 0; i < 16; i++)
        #pragma unroll
        for (int c = 0; c < 4; c++) acc[i][c] = 0.f;

    const float* xbase = Xs + (w * 16) * XS_STRIDE;
    #pragma unroll 4
    for (int k = 0; k < 128; k++) {
        float4 wv = *(const float4*)(Wt + k * XS_STRIDE + lane * 4);
        #pragma unroll
        for (int i = 0; i < 16; i++) {
            float xv = xbase[i * XS_STRIDE + k];
            acc[i][0] += xv * wv.x;
            acc[i][1] += xv * wv.y;
            acc[i][2] += xv * wv.z;
            acc[i][3] += xv * wv.w;
        }
    }

    float4 bb = *(const float4*)(bias + lane * 4);
    #pragma unroll
    for (int i = 0; i < 16; i++) {
        float4 o;
        o.x = acc[i][0] + bb.x;
        o.y = acc[i][1] + bb.y;
        o.z = acc[i][2] + bb.z;
        o.w = acc[i][3] + bb.w;
        *(float4*)(Y + (row0 + w * 16 + i) * DIM + lane * 4) = o;
    }
}

// ---------------- Attention ----------------
// Grid: 192 (b,h,t) * 4 q-parts = 768 CTAs, 256 threads.
// smem: Kt[32][513] transposed K, Vs[512][36], Ps[32][516], Qs[32][33]
#define KT_STRIDE 513
#define VS_STRIDE 36
#define PS_STRIDE 516
#define QS_STRIDE 33
#define OFF_VS (32 * KT_STRIDE)
#define OFF_PS (OFF_VS + 512 * VS_STRIDE)
#define OFF_QS (OFF_PS + 32 * PS_STRIDE)
#define SMEM_ATTN ((OFF_QS + 32 * QS_STRIDE) * 4)

__global__ __launch_bounds__(256, 1)
void attn_kernel(const float* __restrict__ Q, const float* __restrict__ K,
                 const float* __restrict__ V, const int* __restrict__ mask,
                 const float* __restrict__ adjm, float* __restrict__ Xo)
{
    extern __shared__ float sm[];
    float* Kt = sm;
    float* Vs = sm + OFF_VS;
    float* Ps = sm + OFF_PS;
    float* Qs = sm + OFF_QS;

    const int bid = blockIdx.x;
    const int qp  = bid & 3;
    const int bht = bid >> 2;
    const int t   = bht % Tt;
    const int h   = (bht / Tt) & 3;
    const int b   = bht / (Tt * Hh);

    const size_t nb = (size_t)(b * Tt + t) * Nn;   // base btn row for this (b,t)

    const int tid  = threadIdx.x;
    const int w    = tid >> 5;
    const int lane = tid & 31;

    // ---- load K (transposed) and V into smem ----
    #pragma unroll
    for (int it = 0; it < 16; it++) {
        int idx = it * 256 + tid;
        int j4 = idx & 7;
        int m  = idx >> 3;
        float4 kv = *(const float4*)(K + (nb + m) * DIM + h * DK + j4 * 4);
        Kt[(j4 * 4 + 0) * KT_STRIDE + m] = kv.x;
        Kt[(j4 * 4 + 1) * KT_STRIDE + m] = kv.y;
        Kt[(j4 * 4 + 2) * KT_STRIDE + m] = kv.z;
        Kt[(j4 * 4 + 3) * KT_STRIDE + m] = kv.w;
        float4 vv = *(const float4*)(V + (nb + m) * DIM + h * DK + j4 * 4);
        *(float4*)(Vs + m * VS_STRIDE + j4 * 4) = vv;
    }
    __syncthreads();

    const float scale = 0.17677669529663687f;   // 1/sqrt(32)

    for (int qt = 0; qt < 4; qt++) {
        const int n0 = qp * 128 + qt * 32;      // local q-row base in [0,512)

        // ---- stage Q tile (32x32) ----
        {
            int r = tid >> 3, j4 = tid & 7;
            float4 qv = *(const float4*)(Q + (nb + n0 + r) * DIM + h * DK + j4 * 4);
            Qs[r * QS_STRIDE + j4 * 4 + 0] = qv.x;
            Qs[r * QS_STRIDE + j4 * 4 + 1] = qv.y;
            Qs[r * QS_STRIDE + j4 * 4 + 2] = qv.z;
            Qs[r * QS_STRIDE + j4 * 4 + 3] = qv.w;
        }
        __syncthreads();

        // ---- QK^T: warp w owns rows w*4..w*4+3; lane owns cols i*32+lane ----
        float acc[4][16];
        #pragma unroll
        for (int rr = 0; rr < 4; rr++)
            #pragma unroll
            for (int i = 0; i < 16; i++) acc[rr][i] = 0.f;

        #pragma unroll 4
        for (int j = 0; j < 32; j++) {
            float kv[16];
            #pragma unroll
            for (int i = 0; i < 16; i++)
                kv[i] = Kt[j * KT_STRIDE + i * 32 + lane];
            #pragma unroll
            for (int rr = 0; rr < 4; rr++) {
                float qv = Qs[(w * 4 + rr) * QS_STRIDE + j];
                #pragma unroll
                for (int i = 0; i < 16; i++)
                    acc[rr][i] += qv * kv[i];
            }
        }

        // ---- mask + softmax + adjm, write P to smem ----
        #pragma unroll
        for (int rr = 0; rr < 4; rr++) {
            const int n = n0 + w * 4 + rr;
            const int*   mrow = mask + ((nb + n) * Nn);
            const float* arow = adjm + ((nb + n) * Nn);

            float sc[16];
            float mx = -3.0e38f;
            #pragma unroll
            for (int i = 0; i < 16; i++) {
                float s = acc[rr][i] * scale;
                if (mrow[i * 32 + lane] != 0) s = -1.0e9f;
                sc[i] = s;
                mx = fmaxf(mx, s);
            }
            #pragma unroll
            for (int o = 16; o > 0; o >>= 1)
                mx = fmaxf(mx, __shfl_xor_sync(0xffffffffu, mx, o));

            float sum = 0.f;
            #pragma unroll
            for (int i = 0; i < 16; i++) {
                float e = __expf(sc[i] - mx);
                sc[i] = e;
                sum += e;
            }
            #pragma unroll
            for (int o = 16; o > 0; o >>= 1)
                sum += __shfl_xor_sync(0xffffffffu, sum, o);

            float inv = 1.0f / sum;
            #pragma unroll
            for (int i = 0; i < 16; i++) {
                float p = sc[i] * inv * arow[i * 32 + lane];
                Ps[(w * 4 + rr) * PS_STRIDE + i * 32 + lane] = p;
            }
        }
        __syncthreads();

        // ---- PV: thread -> row r = tid/8, cols cg*4..cg*4+3 ----
        {
            const int r  = tid >> 3;
            const int cg = tid & 7;
            float4 o = make_float4(0.f, 0.f, 0.f, 0.f);
            const float* prow = Ps + r * PS_STRIDE;
            #pragma unroll 4
            for (int m4 = 0; m4 < 128; m4++) {
                float4 p4 = *(const float4*)(prow + m4 * 4);
                const float* vb = Vs + (m4 * 4) * VS_STRIDE + cg * 4;
                float4 v0 = *(const float4*)(vb);
                float4 v1 = *(const float4*)(vb + VS_STRIDE);
                float4 v2 = *(const float4*)(vb + 2 * VS_STRIDE);
                float4 v3 = *(const float4*)(vb + 3 * VS_STRIDE);
                o.x += p4.x * v0.x + p4.y * v1.x + p4.z * v2.x + p4.w * v3.x;
                o.y += p4.x * v0.y + p4.y * v1.y + p4.z * v2.y + p4.w * v3.y;
                o.z += p4.x * v0.z + p4.y * v1.z + p4.z * v2.z + p4.w * v3.z;
                o.w += p4.x * v0.w + p4.y * v1.w + p4.z * v2.w + p4.w * v3.w;
            }
            *(float4*)(Xo + (nb + n0 + r) * DIM + h * DK + cg * 4) = o;
        }
        __syncthreads();   // protect Qs/Ps before next tile
    }
}

// ---------------- launcher ----------------
extern "C" void kernel_launch(void* const* d_in, const int* in_sizes, int n_in,
                              void* d_out, int out_size)
{
    const float* query = (const float*)d_in[0];
    const float* key   = (const float*)d_in[1];
    const float* value = (const float*)d_in[2];
    const int*   mask  = (const int*)  d_in[3];
    const float* adjm  = (const float*)d_in[4];
    const float* Wq    = (const float*)d_in[5];
    const float* bq    = (const float*)d_in[6];
    const float* Wk    = (const float*)d_in[7];
    const float* bk    = (const float*)d_in[8];
    const float* Wv    = (const float*)d_in[9];
    const float* bv    = (const float*)d_in[10];
    const float* Wp    = (const float*)d_in[11];
    const float* bp    = (const float*)d_in[12];

    float *pQ, *pK, *pV, *pX;
    cudaGetSymbolAddress((void**)&pQ, g_Q);
    cudaGetSymbolAddress((void**)&pK, g_K);
    cudaGetSymbolAddress((void**)&pV, g_V);
    cudaGetSymbolAddress((void**)&pX, g_X);

    cudaFuncSetAttribute(gemm_kernel, cudaFuncAttributeMaxDynamicSharedMemorySize, SMEM_GEMM);
    cudaFuncSetAttribute(attn_kernel, cudaFuncAttributeMaxDynamicSharedMemorySize, SMEM_ATTN);

    gemm_kernel<<<ROWS / 128, 256, SMEM_GEMM>>>(query, Wq, bq, pQ);
    gemm_kernel<<<ROWS / 128, 256, SMEM_GEMM>>>(key,   Wk, bk, pK);
    gemm_kernel<<<ROWS / 128, 256, SMEM_GEMM>>>(value, Wv, bv, pV);

    attn_kernel<<<Bb * Hh * Tt * 4, 256, SMEM_ATTN>>>(pQ, pK, pV, mask, adjm, pX);

    gemm_kernel<<<ROWS / 128, 256, SMEM_GEMM>>>(pX, Wp, bp, (float*)d_out);
}

// round 2
// speedup vs baseline: 2.1041x; 2.1041x over previous
#include <cuda_runtime.h>
#include <cstdint>

#define Bb   4
#define Tt   12
#define Nn   512
#define DIMM 128
#define DK   32
#define ROWS (Bb*Tt*Nn)          // 24576

// ---------------- scratch ----------------
__device__ float g_Q[ROWS * DIMM];
__device__ float g_K[ROWS * DIMM];
__device__ float g_V[ROWS * DIMM];
__device__ float g_X[ROWS * DIMM];

// ---------------- helpers ----------------
__device__ __forceinline__ float f2tf32(float x) {
    unsigned u;
    asm("cvt.rna.tf32.f32 %0, %1;" : "=r"(u) : "f"(x));
    return __uint_as_float(u);
}

// D = A(16x8 tf32, row) * B(8x8 tf32, col) + D  (fp32 accum)
__device__ __forceinline__ void mma8(float* c,
                                     unsigned a0, unsigned a1, unsigned a2, unsigned a3,
                                     unsigned b0, unsigned b1) {
    asm volatile(
        "mma.sync.aligned.m16n8k8.row.col.f32.tf32.tf32.f32 "
        "{%0,%1,%2,%3}, {%4,%5,%6,%7}, {%8,%9}, {%0,%1,%2,%3};"
        : "+f"(c[0]), "+f"(c[1]), "+f"(c[2]), "+f"(c[3])
        : "r"(a0), "r"(a1), "r"(a2), "r"(a3), "r"(b0), "r"(b1));
}

// perm within each 8-wide k-group: orig col d -> 2*(d&3) + ((d>>2)&1)
// so an LDS.64 at offset 2t reads orig cols (t, t+4) = (frag reg lo, reg hi)

// ================= GEMM: Y[r][e] = sum_d X[r][d]*W[e][d] + b[e] =================
// CTA 128 rows x 128 cols, 256 thr, 8 warps (4m x 2n), warp tile 32x64.
#define GS 136
#define SMEM_GEMM (2 * 128 * GS * 4)

__global__ __launch_bounds__(256, 1)
void gemm_tc(const float* __restrict__ X, const float* __restrict__ W,
             const float* __restrict__ bias, float* __restrict__ Y)
{
    extern __shared__ float sm[];
    float* Xs = sm;               // [128][136] permuted tf32
    float* Ws = sm + 128 * GS;    // [128][136] permuted tf32

    const int tid = threadIdx.x, lane = tid & 31, w = tid >> 5;
    const int g = lane >> 2, t = lane & 3;
    const size_t row0 = (size_t)blockIdx.x * 128;

    #pragma unroll
    for (int i = 0; i < 16; i++) {
        int idx = i * 256 + tid;
        int r = idx >> 5, c4 = idx & 31;
        float4 xv = *(const float4*)(X + (row0 + r) * DIMM + c4 * 4);
        float4 wv = *(const float4*)(W + (size_t)r * DIMM + c4 * 4);
        int kb = c4 * 4;
        int base = kb & ~7, off = (kb & 4) ? 1 : 0;
        float* xd = Xs + r * GS + base + off;
        xd[0] = f2tf32(xv.x); xd[2] = f2tf32(xv.y);
        xd[4] = f2tf32(xv.z); xd[6] = f2tf32(xv.w);
        float* wd = Ws + r * GS + base + off;
        wd[0] = f2tf32(wv.x); wd[2] = f2tf32(wv.y);
        wd[4] = f2tf32(wv.z); wd[6] = f2tf32(wv.w);
    }
    __syncthreads();

    const int mrow0 = (w >> 1) * 32;   // warp m-origin
    const int e0    = (w & 1) * 64;    // warp n-origin

    float acc[2][8][4];
    #pragma unroll
    for (int mt = 0; mt < 2; mt++)
        #pragma unroll
        for (int nt = 0; nt < 8; nt++)
            #pragma unroll
            for (int c = 0; c < 4; c++) acc[mt][nt][c] = 0.f;

    #pragma unroll
    for (int ks = 0; ks < 16; ks++) {
        uint2 aL[2], aH[2];
        #pragma unroll
        for (int mt = 0; mt < 2; mt++) {
            const float* ap = Xs + (mrow0 + 16 * mt + g) * GS + ks * 8 + 2 * t;
            aL[mt] = *(const uint2*)ap;            // a0, a2
            aH[mt] = *(const uint2*)(ap + 8 * GS); // a1, a3
        }
        #pragma unroll
        for (int nt = 0; nt < 8; nt++) {
            uint2 b = *(const uint2*)(Ws + (e0 + 8 * nt + g) * GS + ks * 8 + 2 * t);
            mma8(acc[0][nt], aL[0].x, aH[0].x, aL[0].y, aH[0].y, b.x, b.y);
            mma8(acc[1][nt], aL[1].x, aH[1].x, aL[1].y, aH[1].y, b.x, b.y);
        }
    }

    #pragma unroll
    for (int nt = 0; nt < 8; nt++) {
        float2 bv = *(const float2*)(bias + e0 + 8 * nt + 2 * t);
        #pragma unroll
        for (int mt = 0; mt < 2; mt++) {
            size_t r0 = row0 + mrow0 + 16 * mt + g;
            float2 o0 = make_float2(acc[mt][nt][0] + bv.x, acc[mt][nt][1] + bv.y);
            float2 o1 = make_float2(acc[mt][nt][2] + bv.x, acc[mt][nt][3] + bv.y);
            *(float2*)(Y + r0 * DIMM + e0 + 8 * nt + 2 * t) = o0;
            *(float2*)(Y + (r0 + 8) * DIMM + e0 + 8 * nt + 2 * t) = o1;
        }
    }
}

// ================= Flash attention (tf32 tensor cores) =================
// Grid 768 = (bt:48) x (qp:4) x (h:4), h innermost for L2 reuse of mask/adjm.
// Block 256 thr = 8 warps; warp w owns q-rows 16w..16w+15 of the 128-row block.
// kv chunks of 64, 8 chunks.
#define QSS 40
#define KSS 40
#define VSS 72
#define PSS 72
#define OFF_KS 5120
#define OFF_VT 7680
#define OFF_PS 9984
#define SMEM_ATTN (19200 * 4)

__global__ __launch_bounds__(256, 1)
void attn_tc(const float* __restrict__ Q, const float* __restrict__ K,
             const float* __restrict__ V, const int* __restrict__ mask,
             const float* __restrict__ adjm, float* __restrict__ Xo)
{
    extern __shared__ float sm[];
    float* Qs = sm;             // [128][40] permuted tf32
    float* Ks = sm + OFF_KS;    // [64][40]  permuted tf32
    float* Vt = sm + OFF_VT;    // [32][72]  d-major, kv permuted
    float* Ps = sm + OFF_PS;    // [128][72] kv permuted

    const int tid = threadIdx.x, lane = tid & 31, w = tid >> 5;
    const int g = lane >> 2, t = lane & 3;

    const int bid = blockIdx.x;
    const int h  = bid & 3;
    const int qp = (bid >> 2) & 3;
    const int bt = bid >> 4;
    const size_t nb = (size_t)bt * Nn;
    const int n0 = qp * 128;

    // ---- stage Q block (128x32 -> permuted tf32) ----
    #pragma unroll
    for (int i = 0; i < 4; i++) {
        int idx = i * 256 + tid;
        int r = idx >> 3, c4 = idx & 7;
        float4 qv = *(const float4*)(Q + (nb + n0 + r) * DIMM + h * DK + c4 * 4);
        int kb = c4 * 4, base = kb & ~7, off = (kb & 4) ? 1 : 0;
        float* qd = Qs + r * QSS + base + off;
        qd[0] = f2tf32(qv.x); qd[2] = f2tf32(qv.y);
        qd[4] = f2tf32(qv.z); qd[6] = f2tf32(qv.w);
    }

    float oacc[4][4];
    #pragma unroll
    for (int nt = 0; nt < 4; nt++)
        #pragma unroll
        for (int c = 0; c < 4; c++) oacc[nt][c] = 0.f;

    float m0 = -1e30f, m1 = -1e30f, l0 = 0.f, l1 = 0.f;

    const int qrow0 = n0 + 16 * w + g;           // local q row (lane rows: qrow0, qrow0+8)
    const size_t mrb0 = (nb + qrow0) * (size_t)Nn;
    const size_t mrb1 = mrb0 + 8 * (size_t)Nn;

    // perm positions for C-frag cols 2t and 2t+1 within an 8-group
    const int p0c = 2 * ((2 * t) & 3) + (((2 * t) >> 2) & 1);
    const int p1c = 2 * ((2 * t + 1) & 3) + (((2 * t + 1) >> 2) & 1);

    const float scale = 0.17677669529663687f;    // 1/sqrt(32)

    for (int c = 0; c < 8; c++) {
        __syncthreads();   // prev chunk's Ks/Vt consumers done
        // ---- stage K chunk (permuted) and V chunk (transposed, kv-permuted) ----
        #pragma unroll
        for (int i = 0; i < 2; i++) {
            int idx = i * 256 + tid;
            int r = idx >> 3, c4 = idx & 7;
            float4 kv = *(const float4*)(K + (nb + c * 64 + r) * DIMM + h * DK + c4 * 4);
            int kb = c4 * 4, base = kb & ~7, off = (kb & 4) ? 1 : 0;
            float* kd = Ks + r * KSS + base + off;
            kd[0] = f2tf32(kv.x); kd[2] = f2tf32(kv.y);
            kd[4] = f2tf32(kv.z); kd[6] = f2tf32(kv.w);
            float4 vv = *(const float4*)(V + (nb + c * 64 + r) * DIMM + h * DK + c4 * 4);
            int kvp = (r >> 3) * 8 + 2 * (r & 3) + ((r >> 2) & 1);
            Vt[(c4 * 4 + 0) * VSS + kvp] = f2tf32(vv.x);
            Vt[(c4 * 4 + 1) * VSS + kvp] = f2tf32(vv.y);
            Vt[(c4 * 4 + 2) * VSS + kvp] = f2tf32(vv.z);
            Vt[(c4 * 4 + 3) * VSS + kvp] = f2tf32(vv.w);
        }
        __syncthreads();

        // ---- issue mask/adjm loads early (overlap with QK mma) ----
        int2  mk0[8], mk1[8];
        float2 ad0[8], ad1[8];
        const int colb = c * 64 + 2 * t;
        #pragma unroll
        for (int nt = 0; nt < 8; nt++) {
            int col = colb + 8 * nt;
            mk0[nt] = *(const int2*)  (mask + mrb0 + col);
            mk1[nt] = *(const int2*)  (mask + mrb1 + col);
            ad0[nt] = *(const float2*)(adjm + mrb0 + col);
            ad1[nt] = *(const float2*)(adjm + mrb1 + col);
        }

        // ---- S = Q Kc^T : warp computes 16 x 64 ----
        float sacc[8][4];
        #pragma unroll
        for (int nt = 0; nt < 8; nt++)
            #pragma unroll
            for (int cc = 0; cc < 4; cc++) sacc[nt][cc] = 0.f;

        #pragma unroll
        for (int ks = 0; ks < 4; ks++) {
            const float* ap = Qs + (16 * w + g) * QSS + ks * 8 + 2 * t;
            uint2 aL = *(const uint2*)ap;
            uint2 aH = *(const uint2*)(ap + 8 * QSS);
            #pragma unroll
            for (int nt = 0; nt < 8; nt++) {
                uint2 b = *(const uint2*)(Ks + (8 * nt + g) * KSS + ks * 8 + 2 * t);
                mma8(sacc[nt], aL.x, aH.x, aL.y, aH.y, b.x, b.y);
            }
        }

        // ---- mask + online softmax ----
        float rmax0 = -1e30f, rmax1 = -1e30f;
        #pragma unroll
        for (int nt = 0; nt < 8; nt++) {
            float s0 = sacc[nt][0] * scale; if (mk0[nt].x) s0 = -1e9f;
            float s1 = sacc[nt][1] * scale; if (mk0[nt].y) s1 = -1e9f;
            float s2 = sacc[nt][2] * scale; if (mk1[nt].x) s2 = -1e9f;
            float s3 = sacc[nt][3] * scale; if (mk1[nt].y) s3 = -1e9f;
            sacc[nt][0] = s0; sacc[nt][1] = s1; sacc[nt][2] = s2; sacc[nt][3] = s3;
            rmax0 = fmaxf(rmax0, fmaxf(s0, s1));
            rmax1 = fmaxf(rmax1, fmaxf(s2, s3));
        }
        rmax0 = fmaxf(rmax0, __shfl_xor_sync(0xffffffffu, rmax0, 1));
        rmax0 = fmaxf(rmax0, __shfl_xor_sync(0xffffffffu, rmax0, 2));
        rmax1 = fmaxf(rmax1, __shfl_xor_sync(0xffffffffu, rmax1, 1));
        rmax1 = fmaxf(rmax1, __shfl_xor_sync(0xffffffffu, rmax1, 2));

        float nm0 = fmaxf(m0, rmax0), nm1 = fmaxf(m1, rmax1);
        float al0 = __expf(m0 - nm0), al1 = __expf(m1 - nm1);
        m0 = nm0; m1 = nm1;

        float rs0 = 0.f, rs1 = 0.f;
        float* prow0 = Ps + (16 * w + g) * PSS;
        float* prow1 = prow0 + 8 * PSS;
        #pragma unroll
        for (int nt = 0; nt < 8; nt++) {
            float p0 = __expf(sacc[nt][0] - nm0);
            float p1 = __expf(sacc[nt][1] - nm0);
            float p2 = __expf(sacc[nt][2] - nm1);
            float p3 = __expf(sacc[nt][3] - nm1);
            rs0 += p0 + p1; rs1 += p2 + p3;
            prow0[nt * 8 + p0c] = f2tf32(p0 * ad0[nt].x);
            prow0[nt * 8 + p1c] = f2tf32(p1 * ad0[nt].y);
            prow1[nt * 8 + p0c] = f2tf32(p2 * ad1[nt].x);
            prow1[nt * 8 + p1c] = f2tf32(p3 * ad1[nt].y);
        }
        rs0 += __shfl_xor_sync(0xffffffffu, rs0, 1);
        rs0 += __shfl_xor_sync(0xffffffffu, rs0, 2);
        rs1 += __shfl_xor_sync(0xffffffffu, rs1, 1);
        rs1 += __shfl_xor_sync(0xffffffffu, rs1, 2);
        l0 = l0 * al0 + rs0;
        l1 = l1 * al1 + rs1;

        #pragma unroll
        for (int nt = 0; nt < 4; nt++) {
            oacc[nt][0] *= al0; oacc[nt][1] *= al0;
            oacc[nt][2] *= al1; oacc[nt][3] *= al1;
        }
        __syncwarp();

        // ---- O += P Vc : warp computes 16 x 32 ----
        #pragma unroll
        for (int ks = 0; ks < 8; ks++) {
            const float* ap = Ps + (16 * w + g) * PSS + ks * 8 + 2 * t;
            uint2 aL = *(const uint2*)ap;
            uint2 aH = *(const uint2*)(ap + 8 * PSS);
            #pragma unroll
            for (int nt = 0; nt < 4; nt++) {
                uint2 b = *(const uint2*)(Vt + (8 * nt + g) * VSS + ks * 8 + 2 * t);
                mma8(oacc[nt], aL.x, aH.x, aL.y, aH.y, b.x, b.y);
            }
        }
    }

    // ---- epilogue ----
    float inv0 = 1.f / l0, inv1 = 1.f / l1;
    #pragma unroll
    for (int nt = 0; nt < 4; nt++) {
        float2 o0 = make_float2(oacc[nt][0] * inv0, oacc[nt][1] * inv0);
        float2 o1 = make_float2(oacc[nt][2] * inv1, oacc[nt][3] * inv1);
        *(float2*)(Xo + (nb + qrow0) * DIMM + h * DK + 8 * nt + 2 * t) = o0;
        *(float2*)(Xo + (nb + qrow0 + 8) * DIMM + h * DK + 8 * nt + 2 * t) = o1;
    }
}

// ---------------- launcher ----------------
extern "C" void kernel_launch(void* const* d_in, const int* in_sizes, int n_in,
                              void* d_out, int out_size)
{
    const float* query = (const float*)d_in[0];
    const float* key   = (const float*)d_in[1];
    const float* value = (const float*)d_in[2];
    const int*   mask  = (const int*)  d_in[3];
    const float* adjm  = (const float*)d_in[4];
    const float* Wq    = (const float*)d_in[5];
    const float* bq    = (const float*)d_in[6];
    const float* Wk    = (const float*)d_in[7];
    const float* bk    = (const float*)d_in[8];
    const float* Wv    = (const float*)d_in[9];
    const float* bv    = (const float*)d_in[10];
    const float* Wp    = (const float*)d_in[11];
    const float* bp    = (const float*)d_in[12];

    float *pQ, *pK, *pV, *pX;
    cudaGetSymbolAddress((void**)&pQ, g_Q);
    cudaGetSymbolAddress((void**)&pK, g_K);
    cudaGetSymbolAddress((void**)&pV, g_V);
    cudaGetSymbolAddress((void**)&pX, g_X);

    cudaFuncSetAttribute(gemm_tc, cudaFuncAttributeMaxDynamicSharedMemorySize, SMEM_GEMM);
    cudaFuncSetAttribute(attn_tc, cudaFuncAttributeMaxDynamicSharedMemorySize, SMEM_ATTN);

    gemm_tc<<<ROWS / 128, 256, SMEM_GEMM>>>(query, Wq, bq, pQ);
    gemm_tc<<<ROWS / 128, 256, SMEM_GEMM>>>(key,   Wk, bk, pK);
    gemm_tc<<<ROWS / 128, 256, SMEM_GEMM>>>(value, Wv, bv, pV);

    attn_tc<<<Bb * Tt * 4 * 4, 256, SMEM_ATTN>>>(pQ, pK, pV, mask, adjm, pX);

    gemm_tc<<<ROWS / 128, 256, SMEM_GEMM>>>(pX, Wp, bp, (float*)d_out);
}

// round 4
// speedup vs baseline: 2.8405x; 1.3500x over previous
#include <cuda_runtime.h>
#include <cstdint>

#define Bb   4
#define Tt   12
#define Nn   512
#define DIMM 128
#define DK   32
#define ROWS (Bb*Tt*Nn)          // 24576

// ---------------- scratch ----------------
__device__ float g_Q[ROWS * DIMM];
__device__ float g_K[ROWS * DIMM];
__device__ float g_V[ROWS * DIMM];
__device__ float g_X[ROWS * DIMM];

// ---------------- helpers ----------------
__device__ __forceinline__ float f2tf32(float x) {
    unsigned u;
    asm("cvt.rna.tf32.f32 %0, %1;" : "=r"(u) : "f"(x));
    return __uint_as_float(u);
}

__device__ __forceinline__ void mma8(float* c,
                                     unsigned a0, unsigned a1, unsigned a2, unsigned a3,
                                     unsigned b0, unsigned b1) {
    asm volatile(
        "mma.sync.aligned.m16n8k8.row.col.f32.tf32.tf32.f32 "
        "{%0,%1,%2,%3}, {%4,%5,%6,%7}, {%8,%9}, {%0,%1,%2,%3};"
        : "+f"(c[0]), "+f"(c[1]), "+f"(c[2]), "+f"(c[3])
        : "r"(a0), "r"(a1), "r"(a2), "r"(a3), "r"(b0), "r"(b1));
}

// perm within each 8-wide k-group: orig col d -> 2*(d&3) + ((d>>2)&1)

// ================= GEMM (k-split staging, 2 CTAs/SM) =================
// Y[r][e] = sum_d X[r][d]*W[e][d] + b[e]; CTA 128x128, 256 thr, 8 warps (4m x 2n).
// K staged in two 64-wide halves. blockIdx.y picks (X,W,b,Y) set.
#define GS 72
#define SMEM_GEMM (2 * 128 * GS * 4)

__global__ __launch_bounds__(256, 2)
void gemm_tc(const float* __restrict__ x0, const float* __restrict__ w0,
             const float* __restrict__ bb0, float* __restrict__ y0,
             const float* __restrict__ x1, const float* __restrict__ w1,
             const float* __restrict__ bb1, float* __restrict__ y1,
             const float* __restrict__ x2, const float* __restrict__ w2,
             const float* __restrict__ bb2, float* __restrict__ y2)
{
    extern __shared__ float sm[];
    float* Xs = sm;               // [128][72] permuted tf32 (64-wide half)
    float* Ws = sm + 128 * GS;    // [128][72]

    const float* X = x0; const float* W = w0; const float* bias = bb0; float* Y = y0;
    if (blockIdx.y == 1) { X = x1; W = w1; bias = bb1; Y = y1; }
    else if (blockIdx.y == 2) { X = x2; W = w2; bias = bb2; Y = y2; }

    const int tid = threadIdx.x, lane = tid & 31, w = tid >> 5;
    const int g = lane >> 2, t = lane & 3;
    const size_t row0 = (size_t)blockIdx.x * 128;

    const int mrow0 = (w >> 1) * 32;
    const int e0    = (w & 1) * 64;

    float acc[2][8][4];
    #pragma unroll
    for (int mt = 0; mt < 2; mt++)
        #pragma unroll
        for (int nt = 0; nt < 8; nt++)
            #pragma unroll
            for (int c = 0; c < 4; c++) acc[mt][nt][c] = 0.f;

    for (int kh = 0; kh < 2; kh++) {
        if (kh) __syncthreads();
        // stage 64-wide halves of X and W, permuted tf32
        #pragma unroll
        for (int i = 0; i < 8; i++) {
            int idx = i * 256 + tid;
            int r = idx >> 4, c4 = idx & 15;
            float4 xv = *(const float4*)(X + (row0 + r) * DIMM + kh * 64 + c4 * 4);
            float4 wv = *(const float4*)(W + (size_t)r * DIMM + kh * 64 + c4 * 4);
            int kb = c4 * 4;
            int base = kb & ~7, off = (kb & 4) ? 1 : 0;
            float* xd = Xs + r * GS + base + off;
            xd[0] = f2tf32(xv.x); xd[2] = f2tf32(xv.y);
            xd[4] = f2tf32(xv.z); xd[6] = f2tf32(xv.w);
            float* wd = Ws + r * GS + base + off;
            wd[0] = f2tf32(wv.x); wd[2] = f2tf32(wv.y);
            wd[4] = f2tf32(wv.z); wd[6] = f2tf32(wv.w);
        }
        __syncthreads();

        #pragma unroll
        for (int ks = 0; ks < 8; ks++) {
            uint2 aL[2], aH[2];
            #pragma unroll
            for (int mt = 0; mt < 2; mt++) {
                const float* ap = Xs + (mrow0 + 16 * mt + g) * GS + ks * 8 + 2 * t;
                aL[mt] = *(const uint2*)ap;
                aH[mt] = *(const uint2*)(ap + 8 * GS);
            }
            #pragma unroll
            for (int nt = 0; nt < 8; nt++) {
                uint2 b = *(const uint2*)(Ws + (e0 + 8 * nt + g) * GS + ks * 8 + 2 * t);
                mma8(acc[0][nt], aL[0].x, aH[0].x, aL[0].y, aH[0].y, b.x, b.y);
                mma8(acc[1][nt], aL[1].x, aH[1].x, aL[1].y, aH[1].y, b.x, b.y);
            }
        }
    }

    #pragma unroll
    for (int nt = 0; nt < 8; nt++) {
        float2 bv = *(const float2*)(bias + e0 + 8 * nt + 2 * t);
        #pragma unroll
        for (int mt = 0; mt < 2; mt++) {
            size_t r0 = row0 + mrow0 + 16 * mt + g;
            float2 o0 = make_float2(acc[mt][nt][0] + bv.x, acc[mt][nt][1] + bv.y);
            float2 o1 = make_float2(acc[mt][nt][2] + bv.x, acc[mt][nt][3] + bv.y);
            *(float2*)(Y + r0 * DIMM + e0 + 8 * nt + 2 * t) = o0;
            *(float2*)(Y + (r0 + 8) * DIMM + e0 + 8 * nt + 2 * t) = o1;
        }
    }
}

// ================= Flash attention (tf32, 2 CTAs/SM) =================
#define QSS 40
#define KSS 40
#define VSS 72
#define PSS 72
#define OFF_KS 5120
#define OFF_VT 7680
#define OFF_PS 9984
#define SMEM_ATTN (19200 * 4)

__global__ __launch_bounds__(256, 2)
void attn_tc(const float* __restrict__ Q, const float* __restrict__ K,
             const float* __restrict__ V, const int* __restrict__ mask,
             const float* __restrict__ adjm, float* __restrict__ Xo)
{
    extern __shared__ float sm[];
    float* Qs = sm;             // [128][40]
    float* Ks = sm + OFF_KS;    // [64][40]
    float* Vt = sm + OFF_VT;    // [32][72]
    float* Ps = sm + OFF_PS;    // [128][72]

    const int tid = threadIdx.x, lane = tid & 31, w = tid >> 5;
    const int g = lane >> 2, t = lane & 3;

    const int bid = blockIdx.x;
    const int h  = bid & 3;
    const int qp = (bid >> 2) & 3;
    const int bt = bid >> 4;
    const size_t nb = (size_t)bt * Nn;
    const int n0 = qp * 128;

    // ---- stage Q block ----
    #pragma unroll
    for (int i = 0; i < 4; i++) {
        int idx = i * 256 + tid;
        int r = idx >> 3, c4 = idx & 7;
        float4 qv = *(const float4*)(Q + (nb + n0 + r) * DIMM + h * DK + c4 * 4);
        int kb = c4 * 4, base = kb & ~7, off = (kb & 4) ? 1 : 0;
        float* qd = Qs + r * QSS + base + off;
        qd[0] = f2tf32(qv.x); qd[2] = f2tf32(qv.y);
        qd[4] = f2tf32(qv.z); qd[6] = f2tf32(qv.w);
    }

    float oacc[4][4];
    #pragma unroll
    for (int nt = 0; nt < 4; nt++)
        #pragma unroll
        for (int c = 0; c < 4; c++) oacc[nt][c] = 0.f;

    float m0 = -1e30f, m1 = -1e30f, l0 = 0.f, l1 = 0.f;

    const int qrow0 = n0 + 16 * w + g;
    const size_t mrb0 = (nb + qrow0) * (size_t)Nn;
    const size_t mrb1 = mrb0 + 8 * (size_t)Nn;

    const int p0c = 2 * ((2 * t) & 3) + (((2 * t) >> 2) & 1);
    const int p1c = 2 * ((2 * t + 1) & 3) + (((2 * t + 1) >> 2) & 1);

    const float scale = 0.17677669529663687f;

    for (int c = 0; c < 8; c++) {
        __syncthreads();
        // ---- stage K chunk (permuted) and V chunk (transposed) ----
        #pragma unroll
        for (int i = 0; i < 2; i++) {
            int idx = i * 256 + tid;
            int r = idx >> 3, c4 = idx & 7;
            float4 kv = *(const float4*)(K + (nb + c * 64 + r) * DIMM + h * DK + c4 * 4);
            int kb = c4 * 4, base = kb & ~7, off = (kb & 4) ? 1 : 0;
            float* kd = Ks + r * KSS + base + off;
            kd[0] = f2tf32(kv.x); kd[2] = f2tf32(kv.y);
            kd[4] = f2tf32(kv.z); kd[6] = f2tf32(kv.w);
            float4 vv = *(const float4*)(V + (nb + c * 64 + r) * DIMM + h * DK + c4 * 4);
            int kvp = (r >> 3) * 8 + 2 * (r & 3) + ((r >> 2) & 1);
            Vt[(c4 * 4 + 0) * VSS + kvp] = f2tf32(vv.x);
            Vt[(c4 * 4 + 1) * VSS + kvp] = f2tf32(vv.y);
            Vt[(c4 * 4 + 2) * VSS + kvp] = f2tf32(vv.z);
            Vt[(c4 * 4 + 3) * VSS + kvp] = f2tf32(vv.w);
        }
        __syncthreads();

        // ---- prefetch mask only (adjm loaded post-mask to save regs) ----
        int2 mk0[8], mk1[8];
        const int colb = c * 64 + 2 * t;
        #pragma unroll
        for (int nt = 0; nt < 8; nt++) {
            int col = colb + 8 * nt;
            mk0[nt] = *(const int2*)(mask + mrb0 + col);
            mk1[nt] = *(const int2*)(mask + mrb1 + col);
        }

        // ---- S = Q Kc^T ----
        float sacc[8][4];
        #pragma unroll
        for (int nt = 0; nt < 8; nt++)
            #pragma unroll
            for (int cc = 0; cc < 4; cc++) sacc[nt][cc] = 0.f;

        #pragma unroll
        for (int ks = 0; ks < 4; ks++) {
            const float* ap = Qs + (16 * w + g) * QSS + ks * 8 + 2 * t;
            uint2 aL = *(const uint2*)ap;
            uint2 aH = *(const uint2*)(ap + 8 * QSS);
            #pragma unroll
            for (int nt = 0; nt < 8; nt++) {
                uint2 b = *(const uint2*)(Ks + (8 * nt + g) * KSS + ks * 8 + 2 * t);
                mma8(sacc[nt], aL.x, aH.x, aL.y, aH.y, b.x, b.y);
            }
        }

        // ---- mask + row max; issue adjm loads as mask regs die ----
        float rmax0 = -1e30f, rmax1 = -1e30f;
        float2 ad0[8], ad1[8];
        #pragma unroll
        for (int nt = 0; nt < 8; nt++) {
            float s0 = sacc[nt][0] * scale; if (mk0[nt].x) s0 = -1e9f;
            float s1 = sacc[nt][1] * scale; if (mk0[nt].y) s1 = -1e9f;
            float s2 = sacc[nt][2] * scale; if (mk1[nt].x) s2 = -1e9f;
            float s3 = sacc[nt][3] * scale; if (mk1[nt].y) s3 = -1e9f;
            sacc[nt][0] = s0; sacc[nt][1] = s1; sacc[nt][2] = s2; sacc[nt][3] = s3;
            rmax0 = fmaxf(rmax0, fmaxf(s0, s1));
            rmax1 = fmaxf(rmax1, fmaxf(s2, s3));
            int col = colb + 8 * nt;
            ad0[nt] = *(const float2*)(adjm + mrb0 + col);
            ad1[nt] = *(const float2*)(adjm + mrb1 + col);
        }
        rmax0 = fmaxf(rmax0, __shfl_xor_sync(0xffffffffu, rmax0, 1));
        rmax0 = fmaxf(rmax0, __shfl_xor_sync(0xffffffffu, rmax0, 2));
        rmax1 = fmaxf(rmax1, __shfl_xor_sync(0xffffffffu, rmax1, 1));
        rmax1 = fmaxf(rmax1, __shfl_xor_sync(0xffffffffu, rmax1, 2));

        float nm0 = fmaxf(m0, rmax0), nm1 = fmaxf(m1, rmax1);
        float al0 = __expf(m0 - nm0), al1 = __expf(m1 - nm1);
        m0 = nm0; m1 = nm1;

        float rs0 = 0.f, rs1 = 0.f;
        float* prow0 = Ps + (16 * w + g) * PSS;
        float* prow1 = prow0 + 8 * PSS;
        #pragma unroll
        for (int nt = 0; nt < 8; nt++) {
            float p0 = __expf(sacc[nt][0] - nm0);
            float p1 = __expf(sacc[nt][1] - nm0);
            float p2 = __expf(sacc[nt][2] - nm1);
            float p3 = __expf(sacc[nt][3] - nm1);
            rs0 += p0 + p1; rs1 += p2 + p3;
            prow0[nt * 8 + p0c] = f2tf32(p0 * ad0[nt].x);
            prow0[nt * 8 + p1c] = f2tf32(p1 * ad0[nt].y);
            prow1[nt * 8 + p0c] = f2tf32(p2 * ad1[nt].x);
            prow1[nt * 8 + p1c] = f2tf32(p3 * ad1[nt].y);
        }
        rs0 += __shfl_xor_sync(0xffffffffu, rs0, 1);
        rs0 += __shfl_xor_sync(0xffffffffu, rs0, 2);
        rs1 += __shfl_xor_sync(0xffffffffu, rs1, 1);
        rs1 += __shfl_xor_sync(0xffffffffu, rs1, 2);
        l0 = l0 * al0 + rs0;
        l1 = l1 * al1 + rs1;

        #pragma unroll
        for (int nt = 0; nt < 4; nt++) {
            oacc[nt][0] *= al0; oacc[nt][1] *= al0;
            oacc[nt][2] *= al1; oacc[nt][3] *= al1;
        }
        __syncwarp();

        // ---- O += P Vc ----
        #pragma unroll
        for (int ks = 0; ks < 8; ks++) {
            const float* ap = Ps + (16 * w + g) * PSS + ks * 8 + 2 * t;
            uint2 aL = *(const uint2*)ap;
            uint2 aH = *(const uint2*)(ap + 8 * PSS);
            #pragma unroll
            for (int nt = 0; nt < 4; nt++) {
                uint2 b = *(const uint2*)(Vt + (8 * nt + g) * VSS + ks * 8 + 2 * t);
                mma8(oacc[nt], aL.x, aH.x, aL.y, aH.y, b.x, b.y);
            }
        }
    }

    // ---- epilogue ----
    float inv0 = 1.f / l0, inv1 = 1.f / l1;
    #pragma unroll
    for (int nt = 0; nt < 4; nt++) {
        float2 o0 = make_float2(oacc[nt][0] * inv0, oacc[nt][1] * inv0);
        float2 o1 = make_float2(oacc[nt][2] * inv1, oacc[nt][3] * inv1);
        *(float2*)(Xo + (nb + qrow0) * DIMM + h * DK + 8 * nt + 2 * t) = o0;
        *(float2*)(Xo + (nb + qrow0 + 8) * DIMM + h * DK + 8 * nt + 2 * t) = o1;
    }
}

// ---------------- launcher ----------------
extern "C" void kernel_launch(void* const* d_in, const int* in_sizes, int n_in,
                              void* d_out, int out_size)
{
    const float* query = (const float*)d_in[0];
    const float* key   = (const float*)d_in[1];
    const float* value = (const float*)d_in[2];
    const int*   mask  = (const int*)  d_in[3];
    const float* adjm  = (const float*)d_in[4];
    const float* Wq    = (const float*)d_in[5];
    const float* bq    = (const float*)d_in[6];
    const float* Wk    = (const float*)d_in[7];
    const float* bk    = (const float*)d_in[8];
    const float* Wv    = (const float*)d_in[9];
    const float* bv    = (const float*)d_in[10];
    const float* Wp    = (const float*)d_in[11];
    const float* bp    = (const float*)d_in[12];

    float *pQ, *pK, *pV, *pX;
    cudaGetSymbolAddress((void**)&pQ, g_Q);
    cudaGetSymbolAddress((void**)&pK, g_K);
    cudaGetSymbolAddress((void**)&pV, g_V);
    cudaGetSymbolAddress((void**)&pX, g_X);

    cudaFuncSetAttribute(gemm_tc, cudaFuncAttributeMaxDynamicSharedMemorySize, SMEM_GEMM);
    cudaFuncSetAttribute(attn_tc, cudaFuncAttributeMaxDynamicSharedMemorySize, SMEM_ATTN);

    // fused Q/K/V projections: one launch, blockIdx.y selects
    gemm_tc<<<dim3(ROWS / 128, 3), 256, SMEM_GEMM>>>(
        query, Wq, bq, pQ,
        key,   Wk, bk, pK,
        value, Wv, bv, pV);

    attn_tc<<<Bb * Tt * 4 * 4, 256, SMEM_ATTN>>>(pQ, pK, pV, mask, adjm, pX);

    gemm_tc<<<dim3(ROWS / 128, 1), 256, SMEM_GEMM>>>(
        pX, Wp, bp, (float*)d_out,
        pX, Wp, bp, (float*)d_out,
        pX, Wp, bp, (float*)d_out);
}